// round 2
// baseline (speedup 1.0000x reference)
#include <cuda_runtime.h>
#include <math.h>

#define BB 64
#define SS 512
#define DD 1024
#define HH 1024
#define GG 4096  // 4*H

// Scratch (allocation-free rule: __device__ globals)
__device__ float g_xproj[(size_t)BB * SS * GG];  // 512 MB: [B*S, 4H], m = b*S + t
__device__ float g_h[2][BB * HH];                // ping-pong hidden state
__device__ float g_c[BB * HH];                   // cell state (in-place)

__device__ __forceinline__ float sigmoidf_(float x) {
    return 1.0f / (1.0f + expf(-x));
}

// ---------------------------------------------------------------------------
// init: load h0 -> g_h[0], c0 -> g_c
// ---------------------------------------------------------------------------
__global__ void init_state(const float* __restrict__ h0, const float* __restrict__ c0) {
    int i = blockIdx.x * blockDim.x + threadIdx.x;
    if (i < BB * HH) {
        g_h[0][i] = h0[i];
        g_c[i]    = c0[i];
    }
}

// ---------------------------------------------------------------------------
// xproj: C[M=32768, N=4096] = X[M,K=1024] * Wih[N,K]^T + bias_ih[N]
// 128x128x16 tiles, 256 threads, 8x8 register tile per thread.
// ---------------------------------------------------------------------------
__global__ __launch_bounds__(256) void xproj_kernel(
    const float* __restrict__ X,
    const float* __restrict__ Wih,
    const float* __restrict__ bih)
{
    __shared__ float As[16][128];
    __shared__ float Ws[16][128];

    const int m0 = blockIdx.y * 128;
    const int n0 = blockIdx.x * 128;
    const int tid = threadIdx.x;

    const int lr = tid >> 2;          // 0..63 (row within half-tile)
    const int lk = (tid & 3) * 4;     // 0,4,8,12 (k offset)

    const int ty = tid >> 4;          // 0..15 -> rows ty*8..ty*8+7
    const int tx = tid & 15;          // 0..15 -> cols tx*8..tx*8+7

    float acc[8][8];
#pragma unroll
    for (int i = 0; i < 8; i++)
#pragma unroll
        for (int j = 0; j < 8; j++) acc[i][j] = 0.0f;

    for (int k0 = 0; k0 < DD; k0 += 16) {
#pragma unroll
        for (int h = 0; h < 2; h++) {
            int row = lr + h * 64;
            float4 va = *(const float4*)(X + (size_t)(m0 + row) * DD + k0 + lk);
            As[lk + 0][row] = va.x;
            As[lk + 1][row] = va.y;
            As[lk + 2][row] = va.z;
            As[lk + 3][row] = va.w;
            float4 vw = *(const float4*)(Wih + (size_t)(n0 + row) * DD + k0 + lk);
            Ws[lk + 0][row] = vw.x;
            Ws[lk + 1][row] = vw.y;
            Ws[lk + 2][row] = vw.z;
            Ws[lk + 3][row] = vw.w;
        }
        __syncthreads();

#pragma unroll
        for (int k = 0; k < 16; k++) {
            float a[8], b[8];
            *(float4*)(a + 0) = *(const float4*)&As[k][ty * 8 + 0];
            *(float4*)(a + 4) = *(const float4*)&As[k][ty * 8 + 4];
            *(float4*)(b + 0) = *(const float4*)&Ws[k][tx * 8 + 0];
            *(float4*)(b + 4) = *(const float4*)&Ws[k][tx * 8 + 4];
#pragma unroll
            for (int i = 0; i < 8; i++)
#pragma unroll
                for (int j = 0; j < 8; j++)
                    acc[i][j] += a[i] * b[j];
        }
        __syncthreads();
    }

    // epilogue: add bias_ih, store
    float bv[8];
#pragma unroll
    for (int j = 0; j < 8; j++) bv[j] = bih[n0 + tx * 8 + j];

#pragma unroll
    for (int i = 0; i < 8; i++) {
        int m = m0 + ty * 8 + i;
        float* dst = g_xproj + (size_t)m * GG + n0 + tx * 8;
        float4 v0, v1;
        v0.x = acc[i][0] + bv[0];
        v0.y = acc[i][1] + bv[1];
        v0.z = acc[i][2] + bv[2];
        v0.w = acc[i][3] + bv[3];
        v1.x = acc[i][4] + bv[4];
        v1.y = acc[i][5] + bv[5];
        v1.z = acc[i][6] + bv[6];
        v1.w = acc[i][7] + bv[7];
        *(float4*)(dst + 0) = v0;
        *(float4*)(dst + 4) = v1;
    }
}

// ---------------------------------------------------------------------------
// One LSTM timestep, fully fused:
//   block bx handles j-columns [bx*8, bx*8+8) for ALL 64 batches and all 4 gates
//   (gate tile = 64 batches x 32 gate-cols, col = gate*8 + jj, n = gate*H + j0 + jj)
//   GEMM over K=H=1024, then cell update + output write.
// ---------------------------------------------------------------------------
__global__ __launch_bounds__(256) void lstm_step(
    const float* __restrict__ Whh,
    const float* __restrict__ bhh,
    float* __restrict__ out,
    int t)
{
    __shared__ float As[32][64];       // [k][batch] hidden tile
    __shared__ float Bs[32][32];       // [k][gatecol] weight tile
    __shared__ float gs[64][33];       // [batch][gatecol] gate accum (padded)

    const float* __restrict__ h_in = g_h[t & 1];
    float* __restrict__ h_out = g_h[(t + 1) & 1];

    const int j0 = blockIdx.x * 8;
    const int tid = threadIdx.x;

    const int tr = tid >> 4;   // 0..15 -> rows tr*4..tr*4+3 (batch)
    const int tc = tid & 15;   // 0..15 -> cols tc*2, tc*2+1 (gatecol)

    // loader indices
    const int hb = tid >> 2;          // 0..63 batch row
    const int hk = (tid & 3) * 8;     // k offset (two float4)
    const int wc = tid >> 3;          // 0..31 gatecol
    const int wk = (tid & 7) * 4;     // k offset
    const int wgate = wc >> 3;
    const int wjj = wc & 7;
    const int wn = wgate * HH + j0 + wjj;  // global gate row in Whh

    float acc[4][2];
#pragma unroll
    for (int i = 0; i < 4; i++) { acc[i][0] = 0.0f; acc[i][1] = 0.0f; }

    for (int k0 = 0; k0 < HH; k0 += 32) {
        // load h tile (64 x 32) transposed
        float4 v0 = *(const float4*)(h_in + hb * HH + k0 + hk);
        float4 v1 = *(const float4*)(h_in + hb * HH + k0 + hk + 4);
        As[hk + 0][hb] = v0.x; As[hk + 1][hb] = v0.y;
        As[hk + 2][hb] = v0.z; As[hk + 3][hb] = v0.w;
        As[hk + 4][hb] = v1.x; As[hk + 5][hb] = v1.y;
        As[hk + 6][hb] = v1.z; As[hk + 7][hb] = v1.w;
        // load Whh tile (32 cols x 32 k) transposed
        float4 w = *(const float4*)(Whh + (size_t)wn * HH + k0 + wk);
        Bs[wk + 0][wc] = w.x; Bs[wk + 1][wc] = w.y;
        Bs[wk + 2][wc] = w.z; Bs[wk + 3][wc] = w.w;
        __syncthreads();

#pragma unroll
        for (int k = 0; k < 32; k++) {
            float a[4];
            *(float4*)a = *(const float4*)&As[k][tr * 4];
            float b0 = Bs[k][tc * 2 + 0];
            float b1 = Bs[k][tc * 2 + 1];
#pragma unroll
            for (int i = 0; i < 4; i++) {
                acc[i][0] += a[i] * b0;
                acc[i][1] += a[i] * b1;
            }
        }
        __syncthreads();
    }

    // stash gate partials
#pragma unroll
    for (int i = 0; i < 4; i++) {
        gs[tr * 4 + i][tc * 2 + 0] = acc[i][0];
        gs[tr * 4 + i][tc * 2 + 1] = acc[i][1];
    }
    __syncthreads();

    // pointwise cell update: 64 batches * 8 j-cols = 512 elems, 2 per thread
#pragma unroll
    for (int e = 0; e < 2; e++) {
        int lin = tid * 2 + e;
        int b = lin >> 3;
        int jj = lin & 7;
        int nj = j0 + jj;
        size_t xbase = ((size_t)(b * SS + t)) * GG + nj;

        float gi = gs[b][0 * 8 + jj] + g_xproj[xbase + 0 * HH] + bhh[nj + 0 * HH];
        float gf = gs[b][1 * 8 + jj] + g_xproj[xbase + 1 * HH] + bhh[nj + 1 * HH];
        float gg = gs[b][2 * 8 + jj] + g_xproj[xbase + 2 * HH] + bhh[nj + 2 * HH];
        float go = gs[b][3 * 8 + jj] + g_xproj[xbase + 3 * HH] + bhh[nj + 3 * HH];

        float iv = sigmoidf_(gi);
        float fv = sigmoidf_(gf);
        float gv = tanhf(gg);
        float ov = sigmoidf_(go);

        int ci = b * HH + nj;
        float c = fv * g_c[ci] + iv * gv;
        g_c[ci] = c;
        float h = ov * tanhf(c);
        h_out[ci] = h;
        out[((size_t)b * SS + t) * HH + nj] = h;
    }
}

// ---------------------------------------------------------------------------
// tail: hn then cn after outputs
// ---------------------------------------------------------------------------
__global__ void write_final(float* __restrict__ tail) {
    int i = blockIdx.x * blockDim.x + threadIdx.x;
    if (i < BB * HH) {
        tail[i] = g_h[SS & 1][i];       // h after step S-1 lives in buffer S%2 = 0
        tail[BB * HH + i] = g_c[i];
    }
}

// ---------------------------------------------------------------------------
extern "C" void kernel_launch(void* const* d_in, const int* in_sizes, int n_in,
                              void* d_out, int out_size) {
    const float* X   = (const float*)d_in[0];  // [B,S,D]
    const float* h0  = (const float*)d_in[1];  // [1,B,H]
    const float* c0  = (const float*)d_in[2];  // [1,B,H]
    const float* Wih = (const float*)d_in[3];  // [4H,D]
    const float* Whh = (const float*)d_in[4];  // [4H,H]
    const float* bih = (const float*)d_in[5];  // [4H]
    const float* bhh = (const float*)d_in[6];  // [4H]
    float* out = (float*)d_out;                // outputs [B,S,H] | hn [B,H] | cn [B,H]

    init_state<<<(BB * HH + 255) / 256, 256>>>(h0, c0);

    dim3 gx(GG / 128, (BB * SS) / 128);
    xproj_kernel<<<gx, 256>>>(X, Wih, bih);

    for (int t = 0; t < SS; t++) {
        lstm_step<<<HH / 8, 256>>>(Whh, bhh, out, t);
    }

    write_final<<<(BB * HH + 255) / 256, 256>>>(out + (size_t)BB * SS * HH);
}

// round 6
// speedup vs baseline: 1.3907x; 1.3907x over previous
#include <cuda_runtime.h>
#include <math.h>
#include <stdint.h>

#define BB 64
#define SS 512
#define DD 1024
#define HH 1024
#define GG 4096  // 4*H

// Scratch (allocation-free rule: __device__ globals)
__device__ float g_xproj[(size_t)BB * SS * GG];  // [B*S, 4H], m = b*S + t  (includes bih+bhh)
__device__ float g_h[2][BB * HH];                // ping-pong hidden state (fp32)
__device__ float g_c[BB * HH];                   // cell state (in-place)

__device__ __forceinline__ float sigmoidf_(float x) {
    return 1.0f / (1.0f + expf(-x));
}

__device__ __forceinline__ void cp16(uint32_t s, const void* g) {
    asm volatile("cp.async.cg.shared.global [%0], [%1], 16;\n" :: "r"(s), "l"(g));
}
#define CP_COMMIT() asm volatile("cp.async.commit_group;\n" ::: "memory")
#define CP_WAIT(N)  asm volatile("cp.async.wait_group %0;\n" :: "n"(N) : "memory")

// ---------------------------------------------------------------------------
// init: load h0 -> g_h[0], c0 -> g_c
// ---------------------------------------------------------------------------
__global__ void init_state(const float* __restrict__ h0, const float* __restrict__ c0) {
    int i = blockIdx.x * blockDim.x + threadIdx.x;
    if (i < BB * HH) {
        g_h[0][i] = h0[i];
        g_c[i]    = c0[i];
    }
}

// ---------------------------------------------------------------------------
// xproj: C[M=32768, N=4096] = X[M,K=1024] * Wih[N,K]^T + bias_ih[N] + bias_hh[N]
// 128x128x16 tiles, 256 threads, 8x8 register tile per thread. (fp32)
// ---------------------------------------------------------------------------
__global__ __launch_bounds__(256) void xproj_kernel(
    const float* __restrict__ X,
    const float* __restrict__ Wih,
    const float* __restrict__ bih,
    const float* __restrict__ bhh)
{
    __shared__ float As[16][128];
    __shared__ float Ws[16][128];

    const int m0 = blockIdx.y * 128;
    const int n0 = blockIdx.x * 128;
    const int tid = threadIdx.x;

    const int lr = tid >> 2;          // 0..63
    const int lk = (tid & 3) * 4;     // 0,4,8,12

    const int ty = tid >> 4;          // 0..15
    const int tx = tid & 15;          // 0..15

    float acc[8][8];
#pragma unroll
    for (int i = 0; i < 8; i++)
#pragma unroll
        for (int j = 0; j < 8; j++) acc[i][j] = 0.0f;

    for (int k0 = 0; k0 < DD; k0 += 16) {
#pragma unroll
        for (int h = 0; h < 2; h++) {
            int row = lr + h * 64;
            float4 va = *(const float4*)(X + (size_t)(m0 + row) * DD + k0 + lk);
            As[lk + 0][row] = va.x;
            As[lk + 1][row] = va.y;
            As[lk + 2][row] = va.z;
            As[lk + 3][row] = va.w;
            float4 vw = *(const float4*)(Wih + (size_t)(n0 + row) * DD + k0 + lk);
            Ws[lk + 0][row] = vw.x;
            Ws[lk + 1][row] = vw.y;
            Ws[lk + 2][row] = vw.z;
            Ws[lk + 3][row] = vw.w;
        }
        __syncthreads();

#pragma unroll
        for (int k = 0; k < 16; k++) {
            float a[8], b[8];
            *(float4*)(a + 0) = *(const float4*)&As[k][ty * 8 + 0];
            *(float4*)(a + 4) = *(const float4*)&As[k][ty * 8 + 4];
            *(float4*)(b + 0) = *(const float4*)&Ws[k][tx * 8 + 0];
            *(float4*)(b + 4) = *(const float4*)&Ws[k][tx * 8 + 4];
#pragma unroll
            for (int i = 0; i < 8; i++)
#pragma unroll
                for (int j = 0; j < 8; j++)
                    acc[i][j] += a[i] * b[j];
        }
        __syncthreads();
    }

    float bv[8];
#pragma unroll
    for (int j = 0; j < 8; j++) {
        int n = n0 + tx * 8 + j;
        bv[j] = bih[n] + bhh[n];
    }

#pragma unroll
    for (int i = 0; i < 8; i++) {
        int m = m0 + ty * 8 + i;
        float* dst = g_xproj + (size_t)m * GG + n0 + tx * 8;
        float4 v0, v1;
        v0.x = acc[i][0] + bv[0];
        v0.y = acc[i][1] + bv[1];
        v0.z = acc[i][2] + bv[2];
        v0.w = acc[i][3] + bv[3];
        v1.x = acc[i][4] + bv[4];
        v1.y = acc[i][5] + bv[5];
        v1.z = acc[i][6] + bv[6];
        v1.w = acc[i][7] + bv[7];
        *(float4*)(dst + 0) = v0;
        *(float4*)(dst + 4) = v1;
    }
}

// ---------------------------------------------------------------------------
// One LSTM timestep via tf32 tensor-core MMA.
// Block bx: j-columns [bx*8, bx*8+8), all 64 batches, all 4 gates
//   -> gates GEMM tile: M=64 x N=32 (n = g*1024 + j0 + jj) x K=1024
// K streamed in 128-chunks, double-buffered via cp.async.
// 256 threads = 8 warps; warp w: m-tile mt = w&3 (16 batches), gates gh*2,gh*2+1 (gh=w>>2).
// mma.sync.m16n8k8 tf32 (fp32 in regs, HW truncates mantissa).
// ---------------------------------------------------------------------------
#define KC 128
#define HS_STRIDE 132   // pad for conflict-free fragment LDS
#define HS_ELEMS (64 * HS_STRIDE)         // per buffer
#define WS_ELEMS (32 * HS_STRIDE)         // per buffer
#define SMEM_FLOATS (2 * HS_ELEMS + 2 * WS_ELEMS + 4 * 64 * 8)
#define SMEM_BYTES (SMEM_FLOATS * 4)

__global__ __launch_bounds__(256) void lstm_step_mma(
    const float* __restrict__ Whh,
    float* __restrict__ out,
    int t)
{
    extern __shared__ float sm[];
    float* hs  = sm;                       // [2][64][HS_STRIDE]
    float* ws  = sm + 2 * HS_ELEMS;        // [2][32][HS_STRIDE]
    float* gsm = ws + 2 * WS_ELEMS;        // [4][64][8]

    const float* __restrict__ h_in = g_h[t & 1];
    float* __restrict__ h_out = g_h[(t + 1) & 1];

    const int j0  = blockIdx.x * 8;
    const int tid = threadIdx.x;
    const int wid = tid >> 5;
    const int lane = tid & 31;
    const int gid = lane >> 2;   // 0..7
    const int tg  = lane & 3;    // 0..3

    const int mt = wid & 3;      // m-tile (16 batches)
    const int gh = wid >> 2;     // gate half: gates gh*2, gh*2+1

    const uint32_t hs_s = (uint32_t)__cvta_generic_to_shared(hs);
    const uint32_t ws_s = (uint32_t)__cvta_generic_to_shared(ws);

    // --- async chunk loader: chunk c (k0=c*KC) into buffer buf ---
    auto issue_load = [&](int c, int buf) {
        int k0 = c * KC;
        // h: 64 x 128 floats = 2048 x 16B units, 8 per thread
#pragma unroll
        for (int i = 0; i < 8; i++) {
            int u = tid + i * 256;
            int row = u >> 5;
            int c4  = (u & 31) * 4;
            cp16(hs_s + (uint32_t)(buf * HS_ELEMS + row * HS_STRIDE + c4) * 4,
                 h_in + (size_t)row * HH + k0 + c4);
        }
        // Whh: 32 rows x 128 floats = 1024 units, 4 per thread
#pragma unroll
        for (int i = 0; i < 4; i++) {
            int u = tid + i * 256;
            int r  = u >> 5;
            int c4 = (u & 31) * 4;
            int n  = (r >> 3) * HH + j0 + (r & 7);
            cp16(ws_s + (uint32_t)(buf * WS_ELEMS + r * HS_STRIDE + c4) * 4,
                 Whh + (size_t)n * HH + k0 + c4);
        }
    };

    float c0[4] = {0.f, 0.f, 0.f, 0.f};
    float c1[4] = {0.f, 0.f, 0.f, 0.f};

    issue_load(0, 0);
    CP_COMMIT();

    const int arow0 = mt * 16 + gid;

#pragma unroll 1
    for (int c = 0; c < HH / KC; c++) {
        int cur = c & 1;
        if (c + 1 < HH / KC) {
            issue_load(c + 1, cur ^ 1);
            CP_COMMIT();
            CP_WAIT(1);
        } else {
            CP_WAIT(0);
        }
        __syncthreads();

        const float* hb = hs + cur * HS_ELEMS;
        const float* wb = ws + cur * WS_ELEMS;

#pragma unroll
        for (int ks = 0; ks < KC / 8; ks++) {
            int kb = ks * 8;
            uint32_t a0 = __float_as_uint(hb[(arow0)     * HS_STRIDE + kb + tg]);
            uint32_t a1 = __float_as_uint(hb[(arow0 + 8) * HS_STRIDE + kb + tg]);
            uint32_t a2 = __float_as_uint(hb[(arow0)     * HS_STRIDE + kb + tg + 4]);
            uint32_t a3 = __float_as_uint(hb[(arow0 + 8) * HS_STRIDE + kb + tg + 4]);

            {
                int g = gh * 2;
                uint32_t b0 = __float_as_uint(wb[(g * 8 + gid) * HS_STRIDE + kb + tg]);
                uint32_t b1 = __float_as_uint(wb[(g * 8 + gid) * HS_STRIDE + kb + tg + 4]);
                asm volatile(
                    "mma.sync.aligned.m16n8k8.row.col.f32.tf32.tf32.f32 "
                    "{%0,%1,%2,%3}, {%4,%5,%6,%7}, {%8,%9}, {%0,%1,%2,%3};\n"
                    : "+f"(c0[0]), "+f"(c0[1]), "+f"(c0[2]), "+f"(c0[3])
                    : "r"(a0), "r"(a1), "r"(a2), "r"(a3), "r"(b0), "r"(b1));
            }
            {
                int g = gh * 2 + 1;
                uint32_t b0 = __float_as_uint(wb[(g * 8 + gid) * HS_STRIDE + kb + tg]);
                uint32_t b1 = __float_as_uint(wb[(g * 8 + gid) * HS_STRIDE + kb + tg + 4]);
                asm volatile(
                    "mma.sync.aligned.m16n8k8.row.col.f32.tf32.tf32.f32 "
                    "{%0,%1,%2,%3}, {%4,%5,%6,%7}, {%8,%9}, {%0,%1,%2,%3};\n"
                    : "+f"(c1[0]), "+f"(c1[1]), "+f"(c1[2]), "+f"(c1[3])
                    : "r"(a0), "r"(a1), "r"(a2), "r"(a3), "r"(b0), "r"(b1));
            }
        }
        __syncthreads();
    }

    // stash C tiles: gsm[g][batch][jj]
    {
        int g0 = gh * 2;
        int r0 = mt * 16 + gid;
        gsm[(g0 * 64 + r0)     * 8 + tg * 2 + 0] = c0[0];
        gsm[(g0 * 64 + r0)     * 8 + tg * 2 + 1] = c0[1];
        gsm[(g0 * 64 + r0 + 8) * 8 + tg * 2 + 0] = c0[2];
        gsm[(g0 * 64 + r0 + 8) * 8 + tg * 2 + 1] = c0[3];
        int g1 = g0 + 1;
        gsm[(g1 * 64 + r0)     * 8 + tg * 2 + 0] = c1[0];
        gsm[(g1 * 64 + r0)     * 8 + tg * 2 + 1] = c1[1];
        gsm[(g1 * 64 + r0 + 8) * 8 + tg * 2 + 0] = c1[2];
        gsm[(g1 * 64 + r0 + 8) * 8 + tg * 2 + 1] = c1[3];
    }
    __syncthreads();

    // pointwise cell update: 64 batches * 8 j-cols = 512 elems, 2 per thread
#pragma unroll
    for (int e = 0; e < 2; e++) {
        int lin = tid * 2 + e;
        int b = lin >> 3;
        int jj = lin & 7;
        int nj = j0 + jj;
        size_t xbase = ((size_t)(b * SS + t)) * GG + nj;

        float gi = gsm[(0 * 64 + b) * 8 + jj] + g_xproj[xbase + 0 * HH];
        float gf = gsm[(1 * 64 + b) * 8 + jj] + g_xproj[xbase + 1 * HH];
        float gg = gsm[(2 * 64 + b) * 8 + jj] + g_xproj[xbase + 2 * HH];
        float go = gsm[(3 * 64 + b) * 8 + jj] + g_xproj[xbase + 3 * HH];

        float iv = sigmoidf_(gi);
        float fv = sigmoidf_(gf);
        float gv = tanhf(gg);
        float ov = sigmoidf_(go);

        int ci = b * HH + nj;
        float cc = fv * g_c[ci] + iv * gv;
        g_c[ci] = cc;
        float h = ov * tanhf(cc);
        h_out[ci] = h;
        out[((size_t)b * SS + t) * HH + nj] = h;
    }
}

// ---------------------------------------------------------------------------
// tail: hn then cn after outputs
// ---------------------------------------------------------------------------
__global__ void write_final(float* __restrict__ tail) {
    int i = blockIdx.x * blockDim.x + threadIdx.x;
    if (i < BB * HH) {
        tail[i] = g_h[SS & 1][i];
        tail[BB * HH + i] = g_c[i];
    }
}

// ---------------------------------------------------------------------------
extern "C" void kernel_launch(void* const* d_in, const int* in_sizes, int n_in,
                              void* d_out, int out_size) {
    const float* X   = (const float*)d_in[0];  // [B,S,D]
    const float* h0  = (const float*)d_in[1];  // [1,B,H]
    const float* c0  = (const float*)d_in[2];  // [1,B,H]
    const float* Wih = (const float*)d_in[3];  // [4H,D]
    const float* Whh = (const float*)d_in[4];  // [4H,H]
    const float* bih = (const float*)d_in[5];  // [4H]
    const float* bhh = (const float*)d_in[6];  // [4H]
    float* out = (float*)d_out;                // outputs [B,S,H] | hn [B,H] | cn [B,H]

    cudaFuncSetAttribute(lstm_step_mma,
                         cudaFuncAttributeMaxDynamicSharedMemorySize, SMEM_BYTES);

    init_state<<<(BB * HH + 255) / 256, 256>>>(h0, c0);

    dim3 gx(GG / 128, (BB * SS) / 128);
    xproj_kernel<<<gx, 256>>>(X, Wih, bih, bhh);

    for (int t = 0; t < SS; t++) {
        lstm_step_mma<<<HH / 8, 256, SMEM_BYTES>>>(Whh, out, t);
    }

    write_final<<<(BB * HH + 255) / 256, 256>>>(out + (size_t)BB * SS * HH);
}

// round 7
// speedup vs baseline: 3.7196x; 2.6746x over previous
#include <cuda_runtime.h>
#include <math.h>
#include <stdint.h>

#define BB 64
#define SS 512
#define DD 1024
#define HH 1024
#define GG 4096   // 4*H
#define NBLK 128  // persistent blocks (<=148 SMs, 1 CTA/SM via smem)

// Scratch (allocation-free rule: __device__ globals)
__device__ float g_xproj[(size_t)BB * SS * GG];  // [B*S, 4H], m = b*S + t (includes bih+bhh)
__device__ float g_h[2][BB * HH];                // ping-pong hidden state
__device__ float g_c[BB * HH];                   // cell state
__device__ unsigned int g_bar_count;             // grid barrier
__device__ volatile unsigned int g_bar_gen;

__device__ __forceinline__ float sigmoidf_(float x) {
    return 1.0f / (1.0f + expf(-x));
}

__device__ __forceinline__ void cp16(uint32_t s, const void* g) {
    asm volatile("cp.async.cg.shared.global [%0], [%1], 16;\n" :: "r"(s), "l"(g));
}
#define CP_COMMIT() asm volatile("cp.async.commit_group;\n" ::: "memory")
#define CP_WAIT(N)  asm volatile("cp.async.wait_group %0;\n" :: "n"(N) : "memory")

#define MMA_TF32(C, A, B0, B1)                                               \
    asm volatile(                                                            \
        "mma.sync.aligned.m16n8k8.row.col.f32.tf32.tf32.f32 "                \
        "{%0,%1,%2,%3}, {%4,%5,%6,%7}, {%8,%9}, {%0,%1,%2,%3};\n"            \
        : "+f"((C)[0]), "+f"((C)[1]), "+f"((C)[2]), "+f"((C)[3])             \
        : "r"((A)[0]), "r"((A)[1]), "r"((A)[2]), "r"((A)[3]),                \
          "r"(B0), "r"(B1))

// ---------------------------------------------------------------------------
__global__ void init_state(const float* __restrict__ h0, const float* __restrict__ c0) {
    int i = blockIdx.x * blockDim.x + threadIdx.x;
    if (i < BB * HH) {
        g_h[0][i] = h0[i];
        g_c[i]    = c0[i];
    }
}

// ---------------------------------------------------------------------------
// xproj (tf32 MMA): C[32768, 4096] = X @ Wih^T + (bih + bhh)
// Block tile 128(M) x 64(N), K chunks of 32, double buffered cp.async.
// 8 warps: wm = wid&3 (M 32-rows), wn = wid>>2 (N 32-cols); warp = 32x32.
// ---------------------------------------------------------------------------
#define XBM 128
#define XBN 64
#define XBK 32
#define XSTRIDE 36
#define XA_ELEMS (XBM * XSTRIDE)
#define XB_ELEMS (XBN * XSTRIDE)
#define XSMEM_BYTES ((2 * XA_ELEMS + 2 * XB_ELEMS) * 4)

__global__ __launch_bounds__(256) void xproj_mma(
    const float* __restrict__ X,
    const float* __restrict__ Wih,
    const float* __restrict__ bih,
    const float* __restrict__ bhh)
{
    extern __shared__ float xsm[];
    float* As = xsm;
    float* Bs = xsm + 2 * XA_ELEMS;

    const int m0 = blockIdx.y * XBM;
    const int n0 = blockIdx.x * XBN;
    const int tid = threadIdx.x;
    const int wid = tid >> 5;
    const int lane = tid & 31;
    const int gid = lane >> 2;
    const int tg  = lane & 3;
    const int wm = wid & 3;
    const int wn = wid >> 2;

    const uint32_t As_s = (uint32_t)__cvta_generic_to_shared(As);
    const uint32_t Bs_s = (uint32_t)__cvta_generic_to_shared(Bs);

    auto load_tiles = [&](int k0, int buf) {
#pragma unroll
        for (int i = 0; i < 4; i++) {             // A: 128x32 -> 1024 units
            int u = tid + i * 256;
            int r = u >> 3;
            int c4 = (u & 7) * 4;
            cp16(As_s + (uint32_t)(buf * XA_ELEMS + r * XSTRIDE + c4) * 4,
                 X + (size_t)(m0 + r) * DD + k0 + c4);
        }
#pragma unroll
        for (int i = 0; i < 2; i++) {             // B: 64x32 -> 512 units
            int u = tid + i * 256;
            int r = u >> 3;
            int c4 = (u & 7) * 4;
            cp16(Bs_s + (uint32_t)(buf * XB_ELEMS + r * XSTRIDE + c4) * 4,
                 Wih + (size_t)(n0 + r) * DD + k0 + c4);
        }
    };

    float acc[2][4][4];
#pragma unroll
    for (int a = 0; a < 2; a++)
#pragma unroll
        for (int b = 0; b < 4; b++)
#pragma unroll
            for (int c = 0; c < 4; c++) acc[a][b][c] = 0.0f;

    load_tiles(0, 0);
    CP_COMMIT();

#pragma unroll 1
    for (int kc = 0; kc < DD / XBK; kc++) {
        int cur = kc & 1;
        if (kc + 1 < DD / XBK) {
            load_tiles((kc + 1) * XBK, cur ^ 1);
            CP_COMMIT();
            CP_WAIT(1);
        } else {
            CP_WAIT(0);
        }
        __syncthreads();

        const float* ab = As + cur * XA_ELEMS;
        const float* bb = Bs + cur * XB_ELEMS;

#pragma unroll
        for (int ks = 0; ks < 4; ks++) {
            int kb = ks * 8;
            uint32_t af[2][4];
#pragma unroll
            for (int mi = 0; mi < 2; mi++) {
                int row = wm * 32 + mi * 16 + gid;
                af[mi][0] = __float_as_uint(ab[row * XSTRIDE + kb + tg]);
                af[mi][1] = __float_as_uint(ab[(row + 8) * XSTRIDE + kb + tg]);
                af[mi][2] = __float_as_uint(ab[row * XSTRIDE + kb + tg + 4]);
                af[mi][3] = __float_as_uint(ab[(row + 8) * XSTRIDE + kb + tg + 4]);
            }
#pragma unroll
            for (int ni = 0; ni < 4; ni++) {
                int nrow = wn * 32 + ni * 8 + gid;
                uint32_t b0 = __float_as_uint(bb[nrow * XSTRIDE + kb + tg]);
                uint32_t b1 = __float_as_uint(bb[nrow * XSTRIDE + kb + tg + 4]);
#pragma unroll
                for (int mi = 0; mi < 2; mi++) MMA_TF32(acc[mi][ni], af[mi], b0, b1);
            }
        }
        __syncthreads();
    }

#pragma unroll
    for (int ni = 0; ni < 4; ni++) {
        int n = n0 + wn * 32 + ni * 8 + tg * 2;
        float bv0 = bih[n] + bhh[n];
        float bv1 = bih[n + 1] + bhh[n + 1];
#pragma unroll
        for (int mi = 0; mi < 2; mi++) {
            int m = m0 + wm * 32 + mi * 16 + gid;
            float2 v0 = make_float2(acc[mi][ni][0] + bv0, acc[mi][ni][1] + bv1);
            *(float2*)(g_xproj + (size_t)m * GG + n) = v0;
            float2 v1 = make_float2(acc[mi][ni][2] + bv0, acc[mi][ni][3] + bv1);
            *(float2*)(g_xproj + (size_t)(m + 8) * GG + n) = v1;
        }
    }
}

// ---------------------------------------------------------------------------
// Persistent LSTM: all 512 steps in ONE kernel. 128 blocks, 1/SM.
// Block bx: j-cols [bx*8, bx*8+8), all 64 batches, 4 gates (32 Whh rows).
// Whh slice resident in SMEM (loaded once); c slice resident in SMEM.
// Per step: prefetch xproj tile -> stream h in 128-wide cp.async chunks ->
// tf32 MMA -> fused cell update -> grid barrier.
// ---------------------------------------------------------------------------
#define WS_STRIDE 1028                 // 1024 + 4 -> bank-stride 4 mod 32
#define WS_TOT (32 * WS_STRIDE)        // 32896 floats
#define KC 128
#define HS_STRIDE 132
#define HS_ELEMS (64 * HS_STRIDE)      // per buffer: 8448
#define GSM_ELEMS (4 * 64 * 8)         // 2048
#define CSM_ELEMS 512
#define PSMEM_FLOATS (WS_TOT + 2 * HS_ELEMS + GSM_ELEMS + CSM_ELEMS)
#define PSMEM_BYTES (PSMEM_FLOATS * 4)  // 209408 B

__device__ __forceinline__ void grid_barrier(int tid) {
    __threadfence();
    __syncthreads();
    if (tid == 0) {
        unsigned int gen = g_bar_gen;
        if (atomicAdd(&g_bar_count, 1) == NBLK - 1) {
            g_bar_count = 0;
            __threadfence();
            g_bar_gen = gen + 1;
        } else {
            while (g_bar_gen == gen) { }
        }
    }
    __syncthreads();
}

__global__ __launch_bounds__(256, 1) void lstm_persist(
    const float* __restrict__ Whh,
    float* __restrict__ out)
{
    extern __shared__ float sm[];
    float* ws  = sm;                         // [32][WS_STRIDE] weights (persistent)
    float* hs  = ws + WS_TOT;                // [2][64][HS_STRIDE] h chunks
    float* gsm = hs + 2 * HS_ELEMS;          // [4][64][8] gate tile
    float* csm = gsm + GSM_ELEMS;            // [512] cell slice (persistent)

    const int j0  = blockIdx.x * 8;
    const int tid = threadIdx.x;
    const int wid = tid >> 5;
    const int lane = tid & 31;
    const int gid = lane >> 2;
    const int tg  = lane & 3;
    const int mt = wid & 3;      // m-tile (16 batches)
    const int gh = wid >> 2;     // gate half

    const uint32_t ws_s = (uint32_t)__cvta_generic_to_shared(ws);
    const uint32_t hs_s = (uint32_t)__cvta_generic_to_shared(hs);

    // ---- one-time: load Whh slice (32 rows x 1024) into SMEM ----
#pragma unroll 4
    for (int i = 0; i < 32; i++) {
        int u = tid + i * 256;               // 0..8191 16B-units
        int r = u >> 8;                      // 0..31  (row = g*8 + jj)
        int c4 = (u & 255) * 4;              // 0..1020
        int n = (r >> 3) * HH + j0 + (r & 7);
        cp16(ws_s + (uint32_t)(r * WS_STRIDE + c4) * 4, Whh + (size_t)n * HH + c4);
    }
    CP_COMMIT();

    // ---- one-time: load c slice, precompute per-thread epilogue indices ----
    int b_e[2], nj_e[2], lin_e[2];
    size_t xb_e[2], ob_e[2];
#pragma unroll
    for (int e = 0; e < 2; e++) {
        int lin = tid * 2 + e;
        lin_e[e] = lin;
        b_e[e] = lin >> 3;
        nj_e[e] = j0 + (lin & 7);
        xb_e[e] = (size_t)b_e[e] * SS * GG + nj_e[e];
        ob_e[e] = (size_t)b_e[e] * SS * HH + nj_e[e];
        csm[lin] = g_c[b_e[e] * HH + nj_e[e]];
    }
    CP_WAIT(0);
    __syncthreads();

    const float* wb0 = ws + (size_t)((gh * 2) * 8 + gid) * WS_STRIDE;
    const float* wb1 = ws + (size_t)((gh * 2 + 1) * 8 + gid) * WS_STRIDE;
    const int arow0 = mt * 16 + gid;

#pragma unroll 1
    for (int t = 0; t < SS; t++) {
        const float* __restrict__ h_in = g_h[t & 1];
        float* __restrict__ h_out = g_h[(t + 1) & 1];

        // issue first h chunk
        auto issue_h = [&](int c, int buf) {
            int k0 = c * KC;
#pragma unroll
            for (int i = 0; i < 8; i++) {
                int u = tid + i * 256;
                int row = u >> 5;
                int c4 = (u & 31) * 4;
                cp16(hs_s + (uint32_t)(buf * HS_ELEMS + row * HS_STRIDE + c4) * 4,
                     h_in + (size_t)row * HH + k0 + c4);
            }
        };

        issue_h(0, 0);
        CP_COMMIT();

        // prefetch xproj gate tile for this (block, t): 8 scalars/thread
        float xp[2][4];
#pragma unroll
        for (int e = 0; e < 2; e++)
#pragma unroll
            for (int g = 0; g < 4; g++)
                xp[e][g] = __ldg(&g_xproj[xb_e[e] + (size_t)t * GG + g * HH]);

        float c0[4] = {0.f, 0.f, 0.f, 0.f};
        float c1[4] = {0.f, 0.f, 0.f, 0.f};

#pragma unroll 1
        for (int c = 0; c < HH / KC; c++) {
            int cur = c & 1;
            if (c + 1 < HH / KC) {
                issue_h(c + 1, cur ^ 1);
                CP_COMMIT();
                CP_WAIT(1);
            } else {
                CP_WAIT(0);
            }
            __syncthreads();

            const float* hb = hs + cur * HS_ELEMS;
            const int kg = c * KC;

#pragma unroll
            for (int ks = 0; ks < KC / 8; ks++) {
                int kb = ks * 8;
                uint32_t a[4];
                a[0] = __float_as_uint(hb[(arow0)     * HS_STRIDE + kb + tg]);
                a[1] = __float_as_uint(hb[(arow0 + 8) * HS_STRIDE + kb + tg]);
                a[2] = __float_as_uint(hb[(arow0)     * HS_STRIDE + kb + tg + 4]);
                a[3] = __float_as_uint(hb[(arow0 + 8) * HS_STRIDE + kb + tg + 4]);

                uint32_t b00 = __float_as_uint(wb0[kg + kb + tg]);
                uint32_t b01 = __float_as_uint(wb0[kg + kb + tg + 4]);
                MMA_TF32(c0, a, b00, b01);

                uint32_t b10 = __float_as_uint(wb1[kg + kb + tg]);
                uint32_t b11 = __float_as_uint(wb1[kg + kb + tg + 4]);
                MMA_TF32(c1, a, b10, b11);
            }
            __syncthreads();
        }

        // stash gate tiles: gsm[g][batch][jj]
        {
            int g0 = gh * 2;
            int r0 = mt * 16 + gid;
            gsm[(g0 * 64 + r0)     * 8 + tg * 2 + 0] = c0[0];
            gsm[(g0 * 64 + r0)     * 8 + tg * 2 + 1] = c0[1];
            gsm[(g0 * 64 + r0 + 8) * 8 + tg * 2 + 0] = c0[2];
            gsm[(g0 * 64 + r0 + 8) * 8 + tg * 2 + 1] = c0[3];
            int g1 = g0 + 1;
            gsm[(g1 * 64 + r0)     * 8 + tg * 2 + 0] = c1[0];
            gsm[(g1 * 64 + r0)     * 8 + tg * 2 + 1] = c1[1];
            gsm[(g1 * 64 + r0 + 8) * 8 + tg * 2 + 0] = c1[2];
            gsm[(g1 * 64 + r0 + 8) * 8 + tg * 2 + 1] = c1[3];
        }
        __syncthreads();

        // fused cell update (2 elements per thread)
#pragma unroll
        for (int e = 0; e < 2; e++) {
            int lin = lin_e[e];
            int b = b_e[e];
            int jj = lin & 7;

            float gi = gsm[(0 * 64 + b) * 8 + jj] + xp[e][0];
            float gf = gsm[(1 * 64 + b) * 8 + jj] + xp[e][1];
            float gg = gsm[(2 * 64 + b) * 8 + jj] + xp[e][2];
            float go = gsm[(3 * 64 + b) * 8 + jj] + xp[e][3];

            float iv = sigmoidf_(gi);
            float fv = sigmoidf_(gf);
            float gv = tanhf(gg);
            float ov = sigmoidf_(go);

            float cc = fv * csm[lin] + iv * gv;
            csm[lin] = cc;
            float h = ov * tanhf(cc);
            h_out[b * HH + nj_e[e]] = h;
            out[ob_e[e] + (size_t)t * HH] = h;
        }

        grid_barrier(tid);
    }

    // write back cell state
#pragma unroll
    for (int e = 0; e < 2; e++)
        g_c[b_e[e] * HH + nj_e[e]] = csm[lin_e[e]];
}

// ---------------------------------------------------------------------------
__global__ void write_final(float* __restrict__ tail) {
    int i = blockIdx.x * blockDim.x + threadIdx.x;
    if (i < BB * HH) {
        tail[i] = g_h[SS & 1][i];
        tail[BB * HH + i] = g_c[i];
    }
}

// ---------------------------------------------------------------------------
extern "C" void kernel_launch(void* const* d_in, const int* in_sizes, int n_in,
                              void* d_out, int out_size) {
    const float* X   = (const float*)d_in[0];  // [B,S,D]
    const float* h0  = (const float*)d_in[1];  // [1,B,H]
    const float* c0  = (const float*)d_in[2];  // [1,B,H]
    const float* Wih = (const float*)d_in[3];  // [4H,D]
    const float* Whh = (const float*)d_in[4];  // [4H,H]
    const float* bih = (const float*)d_in[5];  // [4H]
    const float* bhh = (const float*)d_in[6];  // [4H]
    float* out = (float*)d_out;                // outputs [B,S,H] | hn | cn

    cudaFuncSetAttribute(xproj_mma,
                         cudaFuncAttributeMaxDynamicSharedMemorySize, XSMEM_BYTES);
    cudaFuncSetAttribute(lstm_persist,
                         cudaFuncAttributeMaxDynamicSharedMemorySize, PSMEM_BYTES);

    init_state<<<(BB * HH + 255) / 256, 256>>>(h0, c0);

    dim3 gx(GG / XBN, (BB * SS) / XBM);
    xproj_mma<<<gx, 256, XSMEM_BYTES>>>(X, Wih, bih, bhh);

    lstm_persist<<<NBLK, 256, PSMEM_BYTES>>>(Whh, out);

    write_final<<<(BB * HH + 255) / 256, 256>>>(out + (size_t)BB * SS * HH);
}

// round 8
// speedup vs baseline: 3.8982x; 1.0480x over previous
#include <cuda_runtime.h>
#include <math.h>
#include <stdint.h>

#define BB 64
#define SS 512
#define DD 1024
#define HH 1024
#define GG 4096   // 4*H
#define NBLK 128  // persistent blocks (1/SM via smem)

// Scratch (allocation-free rule: __device__ globals)
__device__ float g_xproj[(size_t)BB * SS * GG];  // [B*S, 4H], m = b*S + t (includes bih+bhh)
__device__ float g_h[2][BB * HH];                // ping-pong hidden state
__device__ float g_c[BB * HH];                   // cell state
__device__ unsigned int g_bar_count;             // grid barrier
__device__ volatile unsigned int g_bar_gen;

__device__ __forceinline__ float sigmoidf_(float x) {
    return 1.0f / (1.0f + expf(-x));
}

__device__ __forceinline__ void cp16(uint32_t s, const void* g) {
    asm volatile("cp.async.cg.shared.global [%0], [%1], 16;\n" :: "r"(s), "l"(g));
}
#define CP_COMMIT() asm volatile("cp.async.commit_group;\n" ::: "memory")
#define CP_WAIT(N)  asm volatile("cp.async.wait_group %0;\n" :: "n"(N) : "memory")

#define MMA_TF32(C, A, B0, B1)                                               \
    asm volatile(                                                            \
        "mma.sync.aligned.m16n8k8.row.col.f32.tf32.tf32.f32 "                \
        "{%0,%1,%2,%3}, {%4,%5,%6,%7}, {%8,%9}, {%0,%1,%2,%3};\n"            \
        : "+f"((C)[0]), "+f"((C)[1]), "+f"((C)[2]), "+f"((C)[3])             \
        : "r"((A)[0]), "r"((A)[1]), "r"((A)[2]), "r"((A)[3]),                \
          "r"(B0), "r"(B1))

// ---------------------------------------------------------------------------
__global__ void init_state(const float* __restrict__ h0, const float* __restrict__ c0) {
    int i = blockIdx.x * blockDim.x + threadIdx.x;
    if (i < BB * HH) {
        g_h[0][i] = h0[i];
        g_c[i]    = c0[i];
    }
}

// ---------------------------------------------------------------------------
// xproj (tf32 MMA): C[32768, 4096] = X @ Wih^T + (bih + bhh)
// Block tile 256(M) x 128(N), 512 threads (16 warps), warp tile 64x32.
// K chunks of 32, double-buffered cp.async.
// ---------------------------------------------------------------------------
#define XBM 256
#define XBN 128
#define XBK 32
#define XSTRIDE 36
#define XA_ELEMS (XBM * XSTRIDE)
#define XB_ELEMS (XBN * XSTRIDE)
#define XSMEM_BYTES ((2 * XA_ELEMS + 2 * XB_ELEMS) * 4)

__global__ __launch_bounds__(512) void xproj_mma(
    const float* __restrict__ X,
    const float* __restrict__ Wih,
    const float* __restrict__ bih,
    const float* __restrict__ bhh)
{
    extern __shared__ float xsm[];
    float* As = xsm;
    float* Bs = xsm + 2 * XA_ELEMS;

    const int m0 = blockIdx.y * XBM;
    const int n0 = blockIdx.x * XBN;
    const int tid = threadIdx.x;
    const int wid = tid >> 5;
    const int lane = tid & 31;
    const int gid = lane >> 2;
    const int tg  = lane & 3;
    const int wm = wid & 3;      // m 64-rows
    const int wn = wid >> 2;     // n 32-cols

    const uint32_t As_s = (uint32_t)__cvta_generic_to_shared(As);
    const uint32_t Bs_s = (uint32_t)__cvta_generic_to_shared(Bs);

    auto load_tiles = [&](int k0, int buf) {
#pragma unroll
        for (int i = 0; i < 4; i++) {             // A: 256x32 -> 2048 units
            int u = tid + i * 512;
            int r = u >> 3;
            int c4 = (u & 7) * 4;
            cp16(As_s + (uint32_t)(buf * XA_ELEMS + r * XSTRIDE + c4) * 4,
                 X + (size_t)(m0 + r) * DD + k0 + c4);
        }
#pragma unroll
        for (int i = 0; i < 2; i++) {             // B: 128x32 -> 1024 units
            int u = tid + i * 512;
            int r = u >> 3;
            int c4 = (u & 7) * 4;
            cp16(Bs_s + (uint32_t)(buf * XB_ELEMS + r * XSTRIDE + c4) * 4,
                 Wih + (size_t)(n0 + r) * DD + k0 + c4);
        }
    };

    float acc[4][4][4];
#pragma unroll
    for (int a = 0; a < 4; a++)
#pragma unroll
        for (int b = 0; b < 4; b++)
#pragma unroll
            for (int c = 0; c < 4; c++) acc[a][b][c] = 0.0f;

    load_tiles(0, 0);
    CP_COMMIT();

#pragma unroll 1
    for (int kc = 0; kc < DD / XBK; kc++) {
        int cur = kc & 1;
        if (kc + 1 < DD / XBK) {
            load_tiles((kc + 1) * XBK, cur ^ 1);
            CP_COMMIT();
            CP_WAIT(1);
        } else {
            CP_WAIT(0);
        }
        __syncthreads();

        const float* ab = As + cur * XA_ELEMS;
        const float* bb = Bs + cur * XB_ELEMS;

#pragma unroll
        for (int ks = 0; ks < 4; ks++) {
            int kb = ks * 8;
            uint32_t af[4][4];
#pragma unroll
            for (int mi = 0; mi < 4; mi++) {
                int row = wm * 64 + mi * 16 + gid;
                af[mi][0] = __float_as_uint(ab[row * XSTRIDE + kb + tg]);
                af[mi][1] = __float_as_uint(ab[(row + 8) * XSTRIDE + kb + tg]);
                af[mi][2] = __float_as_uint(ab[row * XSTRIDE + kb + tg + 4]);
                af[mi][3] = __float_as_uint(ab[(row + 8) * XSTRIDE + kb + tg + 4]);
            }
#pragma unroll
            for (int ni = 0; ni < 4; ni++) {
                int nrow = wn * 32 + ni * 8 + gid;
                uint32_t b0 = __float_as_uint(bb[nrow * XSTRIDE + kb + tg]);
                uint32_t b1 = __float_as_uint(bb[nrow * XSTRIDE + kb + tg + 4]);
#pragma unroll
                for (int mi = 0; mi < 4; mi++) MMA_TF32(acc[mi][ni], af[mi], b0, b1);
            }
        }
        __syncthreads();
    }

#pragma unroll
    for (int ni = 0; ni < 4; ni++) {
        int n = n0 + wn * 32 + ni * 8 + tg * 2;
        float bv0 = bih[n] + bhh[n];
        float bv1 = bih[n + 1] + bhh[n + 1];
#pragma unroll
        for (int mi = 0; mi < 4; mi++) {
            int m = m0 + wm * 64 + mi * 16 + gid;
            float2 v0 = make_float2(acc[mi][ni][0] + bv0, acc[mi][ni][1] + bv1);
            *(float2*)(g_xproj + (size_t)m * GG + n) = v0;
            float2 v1 = make_float2(acc[mi][ni][2] + bv0, acc[mi][ni][3] + bv1);
            *(float2*)(g_xproj + (size_t)(m + 8) * GG + n) = v1;
        }
    }
}

// ---------------------------------------------------------------------------
// Persistent LSTM: all 512 steps in ONE kernel. 128 blocks, 1/SM, 512 threads.
// Block bx: j-cols [bx*8, bx*8+8), all 64 batches, 4 gates (32 Whh rows).
// 16 warps = 4 m-tiles x 2 gate-halves x 2 K-halves (partial sums in 2 slabs).
// Whh slice + c slice resident in SMEM. Per step: stream h in 8 chunks
// (each chunk = 64 cols from K-half0 + 64 cols from K-half1) via cp.async,
// tf32 MMA, slab-reduce + fused cell update, grid barrier.
// ---------------------------------------------------------------------------
#define WS_STRIDE 1028                 // 1024+4 -> conflict-free (stride 4 mod 32)
#define WS_TOT (32 * WS_STRIDE)
#define NCH 8                          // chunks per step
#define HS_STRIDE 132
#define HS_ELEMS (64 * HS_STRIDE)      // per buffer (64 rows x 128 cols staged)
#define GSM_ELEMS (2 * 4 * 64 * 8)     // 2 K-half slabs
#define CSM_ELEMS 512
#define PSMEM_FLOATS (WS_TOT + 2 * HS_ELEMS + GSM_ELEMS + CSM_ELEMS)
#define PSMEM_BYTES (PSMEM_FLOATS * 4)  // 217,600 B

__device__ __forceinline__ void grid_barrier(int tid) {
    __threadfence();
    __syncthreads();
    if (tid == 0) {
        unsigned int gen = g_bar_gen;
        if (atomicAdd(&g_bar_count, 1) == NBLK - 1) {
            g_bar_count = 0;
            __threadfence();
            g_bar_gen = gen + 1;
        } else {
            while (g_bar_gen == gen) { }
        }
    }
    __syncthreads();
}

__global__ __launch_bounds__(512, 1) void lstm_persist(
    const float* __restrict__ Whh,
    float* __restrict__ out)
{
    extern __shared__ float sm[];
    float* ws  = sm;                         // [32][WS_STRIDE] weights (persistent)
    float* hs  = ws + WS_TOT;                // [2][64][HS_STRIDE] h chunks
    float* gsm = hs + 2 * HS_ELEMS;          // [2][4][64][8] gate partials
    float* csm = gsm + GSM_ELEMS;            // [512] cell slice (persistent)

    const int j0  = blockIdx.x * 8;
    const int tid = threadIdx.x;
    const int wid = tid >> 5;
    const int lane = tid & 31;
    const int gid = lane >> 2;
    const int tg  = lane & 3;
    const int mt = wid & 3;            // m-tile (16 batches)
    const int gh = (wid >> 2) & 1;     // gate half
    const int kh = wid >> 3;           // K half (0: k<512, 1: k>=512)

    const uint32_t ws_s = (uint32_t)__cvta_generic_to_shared(ws);
    const uint32_t hs_s = (uint32_t)__cvta_generic_to_shared(hs);

    // ---- one-time: load Whh slice (32 rows x 1024) into SMEM ----
#pragma unroll 4
    for (int i = 0; i < 16; i++) {
        int u = tid + i * 512;               // 0..8191 16B-units
        int r = u >> 8;                      // row = g*8 + jj
        int c4 = (u & 255) * 4;
        int n = (r >> 3) * HH + j0 + (r & 7);
        cp16(ws_s + (uint32_t)(r * WS_STRIDE + c4) * 4, Whh + (size_t)n * HH + c4);
    }
    CP_COMMIT();

    // ---- one-time: load c slice, precompute epilogue indices (1 elem/thread) ----
    const int b_e  = tid >> 3;
    const int jj_e = tid & 7;
    const int nj_e = j0 + jj_e;
    const size_t xb_e = (size_t)b_e * SS * GG + nj_e;
    const size_t ob_e = (size_t)b_e * SS * HH + nj_e;
    csm[tid] = g_c[b_e * HH + nj_e];
    CP_WAIT(0);
    __syncthreads();

    const float* wb0 = ws + (size_t)((gh * 2) * 8 + gid) * WS_STRIDE + kh * 512;
    const float* wb1 = ws + (size_t)((gh * 2 + 1) * 8 + gid) * WS_STRIDE + kh * 512;
    const int arow0 = mt * 16 + gid;
    const int kloc = kh * 64;          // this warp's column base inside hs buffer

#pragma unroll 1
    for (int t = 0; t < SS; t++) {
        const float* __restrict__ h_in = g_h[t & 1];
        float* __restrict__ h_out = g_h[(t + 1) & 1];

        // chunk c: hs cols 0-63 <- h[k= c*64 .. +64), cols 64-127 <- h[k= 512+c*64 ..)
        auto issue_h = [&](int c, int buf) {
#pragma unroll
            for (int i = 0; i < 4; i++) {
                int u = tid + i * 512;          // 0..2047 units
                int row = u >> 5;
                int c4 = (u & 31) * 4;          // 0..124
                int gk = (c4 < 64) ? (c * 64 + c4) : (512 + c * 64 + (c4 - 64));
                cp16(hs_s + (uint32_t)(buf * HS_ELEMS + row * HS_STRIDE + c4) * 4,
                     h_in + (size_t)row * HH + gk);
            }
        };

        issue_h(0, 0);
        CP_COMMIT();

        // prefetch xproj gate tile for this (block, t): 4 scalars/thread
        float xp[4];
#pragma unroll
        for (int g = 0; g < 4; g++)
            xp[g] = __ldg(&g_xproj[xb_e + (size_t)t * GG + g * HH]);

        float c0[4] = {0.f, 0.f, 0.f, 0.f};
        float c1[4] = {0.f, 0.f, 0.f, 0.f};

#pragma unroll 1
        for (int c = 0; c < NCH; c++) {
            int cur = c & 1;
            if (c + 1 < NCH) {
                issue_h(c + 1, cur ^ 1);
                CP_COMMIT();
                CP_WAIT(1);
            } else {
                CP_WAIT(0);
            }
            __syncthreads();

            const float* hb = hs + cur * HS_ELEMS;
            const int kg = c * 64;             // k offset within this warp's K-half

#pragma unroll
            for (int ks = 0; ks < 8; ks++) {
                int kb = kloc + ks * 8;
                uint32_t a[4];
                a[0] = __float_as_uint(hb[(arow0)     * HS_STRIDE + kb + tg]);
                a[1] = __float_as_uint(hb[(arow0 + 8) * HS_STRIDE + kb + tg]);
                a[2] = __float_as_uint(hb[(arow0)     * HS_STRIDE + kb + tg + 4]);
                a[3] = __float_as_uint(hb[(arow0 + 8) * HS_STRIDE + kb + tg + 4]);

                uint32_t b00 = __float_as_uint(wb0[kg + ks * 8 + tg]);
                uint32_t b01 = __float_as_uint(wb0[kg + ks * 8 + tg + 4]);
                MMA_TF32(c0, a, b00, b01);

                uint32_t b10 = __float_as_uint(wb1[kg + ks * 8 + tg]);
                uint32_t b11 = __float_as_uint(wb1[kg + ks * 8 + tg + 4]);
                MMA_TF32(c1, a, b10, b11);
            }
            __syncthreads();
        }

        // stash partials: gsm[kh][g][batch][jj]
        {
            int g0 = gh * 2;
            int r0 = mt * 16 + gid;
            float* gs = gsm + kh * (4 * 64 * 8);
            gs[(g0 * 64 + r0)     * 8 + tg * 2 + 0] = c0[0];
            gs[(g0 * 64 + r0)     * 8 + tg * 2 + 1] = c0[1];
            gs[(g0 * 64 + r0 + 8) * 8 + tg * 2 + 0] = c0[2];
            gs[(g0 * 64 + r0 + 8) * 8 + tg * 2 + 1] = c0[3];
            int g1 = g0 + 1;
            gs[(g1 * 64 + r0)     * 8 + tg * 2 + 0] = c1[0];
            gs[(g1 * 64 + r0)     * 8 + tg * 2 + 1] = c1[1];
            gs[(g1 * 64 + r0 + 8) * 8 + tg * 2 + 0] = c1[2];
            gs[(g1 * 64 + r0 + 8) * 8 + tg * 2 + 1] = c1[3];
        }
        __syncthreads();

        // fused cell update (1 element per thread; sum the two K-half slabs)
        {
            const float* s0 = gsm;
            const float* s1 = gsm + (4 * 64 * 8);
            int base = b_e * 8 + jj_e;

            float gi = s0[(0 * 64) * 8 + base] + s1[(0 * 64) * 8 + base] + xp[0];
            float gf = s0[(1 * 64) * 8 + base] + s1[(1 * 64) * 8 + base] + xp[1];
            float gg = s0[(2 * 64) * 8 + base] + s1[(2 * 64) * 8 + base] + xp[2];
            float go = s0[(3 * 64) * 8 + base] + s1[(3 * 64) * 8 + base] + xp[3];

            float iv = sigmoidf_(gi);
            float fv = sigmoidf_(gf);
            float gv = tanhf(gg);
            float ov = sigmoidf_(go);

            float cc = fv * csm[tid] + iv * gv;
            csm[tid] = cc;
            float h = ov * tanhf(cc);
            h_out[b_e * HH + nj_e] = h;
            out[ob_e + (size_t)t * HH] = h;
        }

        grid_barrier(tid);
    }

    // write back cell state
    g_c[b_e * HH + nj_e] = csm[tid];
}

// ---------------------------------------------------------------------------
__global__ void write_final(float* __restrict__ tail) {
    int i = blockIdx.x * blockDim.x + threadIdx.x;
    if (i < BB * HH) {
        tail[i] = g_h[SS & 1][i];
        tail[BB * HH + i] = g_c[i];
    }
}

// ---------------------------------------------------------------------------
extern "C" void kernel_launch(void* const* d_in, const int* in_sizes, int n_in,
                              void* d_out, int out_size) {
    const float* X   = (const float*)d_in[0];  // [B,S,D]
    const float* h0  = (const float*)d_in[1];  // [1,B,H]
    const float* c0  = (const float*)d_in[2];  // [1,B,H]
    const float* Wih = (const float*)d_in[3];  // [4H,D]
    const float* Whh = (const float*)d_in[4];  // [4H,H]
    const float* bih = (const float*)d_in[5];  // [4H]
    const float* bhh = (const float*)d_in[6];  // [4H]
    float* out = (float*)d_out;                // outputs [B,S,H] | hn | cn

    cudaFuncSetAttribute(xproj_mma,
                         cudaFuncAttributeMaxDynamicSharedMemorySize, XSMEM_BYTES);
    cudaFuncSetAttribute(lstm_persist,
                         cudaFuncAttributeMaxDynamicSharedMemorySize, PSMEM_BYTES);

    init_state<<<(BB * HH + 255) / 256, 256>>>(h0, c0);

    dim3 gx(GG / XBN, (BB * SS) / XBM);
    xproj_mma<<<gx, 512, XSMEM_BYTES>>>(X, Wih, bih, bhh);

    lstm_persist<<<NBLK, 512, PSMEM_BYTES>>>(Whh, out);

    write_final<<<(BB * HH + 255) / 256, 256>>>(out + (size_t)BB * SS * HH);
}